// round 14
// baseline (speedup 1.0000x reference)
#include <cuda_runtime.h>
#include <cuda_bf16.h>
#include <cuda_fp16.h>
#include <stdint.h>
#include <math.h>

#define TT 2048
#define HDIM 2048
#define NHEADS 32
#define NKVH 8
#define HEADD 64
#define SWIN 128
#define QKVD 3072   // HEADD * (NHEADS + 2*NKVH)

// ---------------- scratch (device globals; no allocation allowed) ----------------
__device__ __half g_qkvh[(size_t)TT * QKVD];   // qkv, fp16 (pre-rope)
__device__ __half g_nh[TT * HDIM];             // rmsnorm out, fp16
__device__ __half g_ah[TT * HDIM];             // attention out, fp16
__device__ __half g_wqh[(size_t)HDIM * QKVD];  // qkv weight fp16, transposed [N][K]
__device__ __half g_woh[(size_t)HDIM * HDIM];  // out weight fp16, transposed [N][K]

// ---------------- weight transpose to fp16: W[K][N] -> Wh[N][K] ---------
__global__ void splitwh_t(const float* __restrict__ W,
                          __half* __restrict__ Wh, int K, int N) {
    __shared__ float tile[32][33];
    const int kb = blockIdx.y * 32, nb = blockIdx.x * 32;
    const int tx = threadIdx.x, ty = threadIdx.y;   // 32 x 8
    #pragma unroll
    for (int i = 0; i < 32; i += 8)
        tile[ty + i][tx] = W[(size_t)(kb + ty + i) * N + nb + tx];
    __syncthreads();
    #pragma unroll
    for (int i = 0; i < 32; i += 8) {
        int n = nb + ty + i, k = kb + tx;
        Wh[(size_t)n * K + k] = __float2half(tile[tx][ty + i]);
    }
}

// ---------------- RMSNorm (writes fp16) ----------------
__global__ void rmsnorm_kernel(const float* __restrict__ x,
                               const float* __restrict__ scale) {
    int t = blockIdx.x;
    const float* row = x + (size_t)t * HDIM;
    float ss = 0.f;
    for (int i = threadIdx.x; i < HDIM; i += blockDim.x) {
        float v = row[i];
        ss += v * v;
    }
    __shared__ float sh[9];
    #pragma unroll
    for (int o = 16; o; o >>= 1) ss += __shfl_xor_sync(0xffffffffu, ss, o);
    int lane = threadIdx.x & 31, wid = threadIdx.x >> 5;
    if (lane == 0) sh[wid] = ss;
    __syncthreads();
    if (threadIdx.x == 0) {
        float s = 0.f;
        for (int i = 0; i < (int)(blockDim.x >> 5); i++) s += sh[i];
        sh[8] = rsqrtf(s / (float)HDIM + 1e-5f);
    }
    __syncthreads();
    float inv = sh[8];
    for (int i = threadIdx.x; i < HDIM; i += blockDim.x)
        g_nh[(size_t)t * HDIM + i] = __float2half(row[i] * inv * scale[i]);
}

// ---------------- GEMM pieces -------------------------------------------
#define MMAF(d, a, b0, b1) asm volatile( \
  "mma.sync.aligned.m16n8k16.row.col.f32.f16.f16.f32 " \
  "{%0,%1,%2,%3},{%4,%5,%6,%7},{%8,%9},{%0,%1,%2,%3};\n" \
  : "+f"((d)[0]), "+f"((d)[1]), "+f"((d)[2]), "+f"((d)[3]) \
  : "r"((a)[0]), "r"((a)[1]), "r"((a)[2]), "r"((a)[3]), \
    "r"(b0), "r"(b1))

#define LDSM4(r, addr) asm volatile( \
  "ldmatrix.sync.aligned.m8n8.x4.shared.b16 {%0,%1,%2,%3}, [%4];" \
  : "=r"((r)[0]), "=r"((r)[1]), "=r"((r)[2]), "=r"((r)[3]) : "r"(addr))

#define SROWB 80u                 // padded row stride in bytes (40 halves)
#define SAB   (128u * SROWB)      // 10240 B per array
#define STAGEB2 (2u * SAB)        // A,B
#define GSMEM_BYTES2 (2 * STAGEB2)   // 40960

extern __shared__ unsigned char dynsm[];

// ---------------- fp16 1-term GEMM: A @ Bh + bias; out fp32 (+resid) or fp16 ----
__global__ __launch_bounds__(512, 2) void gemm_f16_1(
    const __half* __restrict__ A, const __half* __restrict__ Bh,
    const float* __restrict__ bias, const float* __restrict__ resid,
    float* __restrict__ C, __half* __restrict__ Ch, int N, int K)
{
    const int tid  = threadIdx.x;
    const int lane = tid & 31;
    const int wid  = tid >> 5;
    const int grp  = lane >> 2;
    const int qid  = lane & 3;
    const int wm   = (wid >> 2) * 32;
    const int wn   = (wid & 3) * 32;
    const int m0 = blockIdx.y * 128;
    const int n0 = blockIdx.x * 128;

    uint32_t smb;
    asm("{ .reg .u64 t; cvta.to.shared.u64 t, %1; cvt.u32.u64 %0, t; }"
        : "=r"(smb) : "l"(dynsm));

    float acc[2][4][4];
    #pragma unroll
    for (int i = 0; i < 2; i++)
        #pragma unroll
        for (int j = 0; j < 4; j++)
            #pragma unroll
            for (int r = 0; r < 4; r++) acc[i][j][r] = 0.f;

    const int lrow = tid >> 2, lc16 = tid & 3;

    auto load_stage = [&](int stage, int t) {
        const int k0 = t << 5;
        const uint32_t sb = smb + stage * STAGEB2;
        {
            const __half* src = A + (size_t)(m0 + lrow) * K + k0 + lc16 * 8;
            uint32_t dst = sb + lrow * SROWB + lc16 * 16;
            asm volatile("cp.async.cg.shared.global [%0], [%1], 16;" :: "r"(dst), "l"(src));
        }
        {
            const __half* src = Bh + (size_t)(n0 + lrow) * K + k0 + lc16 * 8;
            uint32_t dst = sb + SAB + lrow * SROWB + lc16 * 16;
            asm volatile("cp.async.cg.shared.global [%0], [%1], 16;" :: "r"(dst), "l"(src));
        }
        asm volatile("cp.async.commit_group;");
    };

    const uint32_t lmrow = lane & 15;
    const uint32_t lmkh  = (lane >> 4) * 16;
    const uint32_t aoff0 = (wm + 0  + lmrow) * SROWB + lmkh;
    const uint32_t aoff1 = (wm + 16 + lmrow) * SROWB + lmkh;
    const uint32_t boff0 = (wn + 0  + lmrow) * SROWB + lmkh;
    const uint32_t boff1 = (wn + 16 + lmrow) * SROWB + lmkh;

    const int trips = K >> 5;
    load_stage(0, 0);
    load_stage(1, 1);

    for (int t = 0; t < trips; t++) {
        if (t < trips - 1) asm volatile("cp.async.wait_group 1;");
        else               asm volatile("cp.async.wait_group 0;");
        __syncthreads();

        const uint32_t sb = smb + (t & 1) * STAGEB2;
        #pragma unroll
        for (int ks = 0; ks < 2; ks++) {
            const uint32_t ko = ks * 32;
            uint32_t ah[2][4];
            LDSM4(ah[0], sb + aoff0 + ko);
            LDSM4(ah[1], sb + aoff1 + ko);
            #pragma unroll
            for (int np = 0; np < 2; np++) {
                uint32_t bh[4];
                LDSM4(bh, sb + SAB + (np ? boff1 : boff0) + ko);
                #pragma unroll
                for (int mt = 0; mt < 2; mt++) {
                    #pragma unroll
                    for (int sub = 0; sub < 2; sub++) {
                        float* d = acc[mt][np * 2 + sub];
                        MMAF(d, ah[mt], bh[sub], bh[sub + 2]);
                    }
                }
            }
        }
        __syncthreads();
        if (t + 2 < trips) load_stage(t & 1, t + 2);
    }

    #pragma unroll
    for (int mt = 0; mt < 2; mt++) {
        int r0 = m0 + wm + mt * 16 + grp;
        #pragma unroll
        for (int nt = 0; nt < 4; nt++) {
            int c = n0 + wn + nt * 8 + qid * 2;
            float2 bb = *(const float2*)&bias[c];
            float2 v0 = make_float2(acc[mt][nt][0] + bb.x, acc[mt][nt][1] + bb.y);
            float2 v1 = make_float2(acc[mt][nt][2] + bb.x, acc[mt][nt][3] + bb.y);
            if (Ch) {
                *(__half2*)&Ch[(size_t)r0 * N + c]       = __floats2half2_rn(v0.x, v0.y);
                *(__half2*)&Ch[(size_t)(r0 + 8) * N + c] = __floats2half2_rn(v1.x, v1.y);
            } else {
                float2 ra = *(const float2*)&resid[(size_t)r0 * N + c];
                float2 rb = *(const float2*)&resid[(size_t)(r0 + 8) * N + c];
                v0.x += ra.x; v0.y += ra.y; v1.x += rb.x; v1.y += rb.y;
                *(float2*)&C[(size_t)r0 * N + c]       = v0;
                *(float2*)&C[(size_t)(r0 + 8) * N + c] = v1;
            }
        }
    }
}

// ---------------- attention: rope fused in staging, fp16 K/V in smem ----------
// grid (64 q-tiles, 8 kv heads), 512 threads; 4 GQA heads x 4 warps each;
// warp handles 8 q in two groups of 4 (loads amortized across the group).
#define KT2S 82                  // uint (half2) per K^T row (>= 80, even)
#define VS2  33                  // uint (half2) per V row (32 pairs + pad)
#define KT_STRIDE 164            // fp32 score row stride
#define KMAX 160
#define ATT5_BYTES ((64 * KT2S + 160 * VS2 + 4 * 32 * 64 + 16 * 4 * KT_STRIDE) * 4)

__global__ __launch_bounds__(512, 1) void attn5_kernel(
    const float* __restrict__ sinks,
    const float* __restrict__ cos_t, const float* __restrict__ sin_t)
{
    uint32_t* KsT2 = (uint32_t*)dynsm;             // [64][KT2S] half2, KsT2h[d][k]
    uint32_t* Vs2  = KsT2 + 64 * KT2S;             // [160][VS2] half2, dims paired
    float*    Qs   = (float*)(Vs2 + 160 * VS2);    // [4][32][64] fp32 (rope applied)
    float*    S    = Qs + 4 * 32 * 64;             // [16][4][KT_STRIDE]
    __half*   KsTh = (__half*)KsT2;                // half view, row stride 2*KT2S

    const int qt = blockIdx.x;
    const int n  = blockIdx.y;
    const int q0 = qt * 32;
    const int k0 = (q0 - SWIN > 0) ? (q0 - SWIN) : 0;
    const int kcnt = q0 + 32 - k0;
    const int tid = threadIdx.x;
    const int lane = tid & 31, wid = tid >> 5;

    const __half* qkvh = g_qkvh;
    const int kcol = NHEADS * HEADD + n * HEADD;
    const int vcol = kcol + NKVH * HEADD;

    // ---- stage K with rope (fp16 -> rope fp32 -> fp16, transposed) ----
    for (int f = tid; f < kcnt * 8; f += 512) {
        int r = f >> 3, d0 = (f & 7) * 4;
        const __half* src = qkvh + (size_t)(k0 + r) * QKVD + kcol;
        uint2 w1 = *(const uint2*)(src + d0);
        uint2 w2 = *(const uint2*)(src + d0 + 32);
        float2 a0 = __half22float2(*(__half2*)&w1.x);
        float2 a1 = __half22float2(*(__half2*)&w1.y);
        float2 b0 = __half22float2(*(__half2*)&w2.x);
        float2 b1 = __half22float2(*(__half2*)&w2.y);
        float4 cs = *(const float4*)&cos_t[(size_t)(k0 + r) * 32 + d0];
        float4 sn = *(const float4*)&sin_t[(size_t)(k0 + r) * 32 + d0];
        KsTh[(d0 + 0) * (2 * KT2S) + r] = __float2half(a0.x * cs.x - b0.x * sn.x);
        KsTh[(d0 + 1) * (2 * KT2S) + r] = __float2half(a0.y * cs.y - b0.y * sn.y);
        KsTh[(d0 + 2) * (2 * KT2S) + r] = __float2half(a1.x * cs.z - b1.x * sn.z);
        KsTh[(d0 + 3) * (2 * KT2S) + r] = __float2half(a1.y * cs.w - b1.y * sn.w);
        KsTh[(d0 + 32) * (2 * KT2S) + r] = __float2half(b0.x * cs.x + a0.x * sn.x);
        KsTh[(d0 + 33) * (2 * KT2S) + r] = __float2half(b0.y * cs.y + a0.y * sn.y);
        KsTh[(d0 + 34) * (2 * KT2S) + r] = __float2half(b1.x * cs.z + a1.x * sn.z);
        KsTh[(d0 + 35) * (2 * KT2S) + r] = __float2half(b1.y * cs.w + a1.y * sn.w);
    }
    // ---- stage V (straight fp16 copy, dim-paired) ----
    for (int f = tid; f < kcnt * 16; f += 512) {
        int r = f >> 4, d0 = (f & 15) * 4;
        uint2 w = *(const uint2*)(qkvh + (size_t)(k0 + r) * QKVD + vcol + d0);
        Vs2[r * VS2 + (d0 >> 1)]     = w.x;
        Vs2[r * VS2 + (d0 >> 1) + 1] = w.y;
    }
    // ---- stage Q with rope (fp32 in smem, broadcast-read later) ----
    for (int f = tid; f < 4 * 32 * 8; f += 512) {
        int g = f >> 8, rem = f & 255, r = rem >> 3, d0 = (rem & 7) * 4;
        const __half* src = qkvh + (size_t)(q0 + r) * QKVD + (n * 4 + g) * HEADD;
        uint2 w1 = *(const uint2*)(src + d0);
        uint2 w2 = *(const uint2*)(src + d0 + 32);
        float2 a0 = __half22float2(*(__half2*)&w1.x);
        float2 a1 = __half22float2(*(__half2*)&w1.y);
        float2 b0 = __half22float2(*(__half2*)&w2.x);
        float2 b1 = __half22float2(*(__half2*)&w2.y);
        float4 cs = *(const float4*)&cos_t[(size_t)(q0 + r) * 32 + d0];
        float4 sn = *(const float4*)&sin_t[(size_t)(q0 + r) * 32 + d0];
        float* qrow = Qs + (g * 32 + r) * 64;
        qrow[d0 + 0] = a0.x * cs.x - b0.x * sn.x;
        qrow[d0 + 1] = a0.y * cs.y - b0.y * sn.y;
        qrow[d0 + 2] = a1.x * cs.z - b1.x * sn.z;
        qrow[d0 + 3] = a1.y * cs.w - b1.y * sn.w;
        qrow[d0 + 32] = b0.x * cs.x + a0.x * sn.x;
        qrow[d0 + 33] = b0.y * cs.y + a0.y * sn.y;
        qrow[d0 + 34] = b1.x * cs.z + a1.x * sn.z;
        qrow[d0 + 35] = b1.y * cs.w + a1.y * sn.w;
    }
    __syncthreads();

    const int g  = wid & 3;
    const int ww = wid >> 2;
    const int h  = n * 4 + g;
    const float snk = sinks[h];
    float* S4 = S + wid * 4 * KT_STRIDE;

    #pragma unroll
    for (int qq = 0; qq < 2; qq++) {
        const int qi0 = ww * 8 + qq * 4;
        float lmax[4] = {-INFINITY, -INFINITY, -INFINITY, -INFINITY};

        // ---- score pass ----
        for (int kb = lane; kb < 40; kb += 32) {
            const int kk = kb * 4, jj = kk >> 1;
            float sc[4][4];
            #pragma unroll
            for (int p = 0; p < 4; p++)
                sc[p][0] = sc[p][1] = sc[p][2] = sc[p][3] = 0.f;
            #pragma unroll
            for (int d = 0; d < 64; d += 4) {
                uint2 kw0 = *(const uint2*)&KsT2[(d + 0) * KT2S + jj];
                uint2 kw1 = *(const uint2*)&KsT2[(d + 1) * KT2S + jj];
                uint2 kw2 = *(const uint2*)&KsT2[(d + 2) * KT2S + jj];
                uint2 kw3 = *(const uint2*)&KsT2[(d + 3) * KT2S + jj];
                float2 k0a = __half22float2(*(__half2*)&kw0.x), k0b = __half22float2(*(__half2*)&kw0.y);
                float2 k1a = __half22float2(*(__half2*)&kw1.x), k1b = __half22float2(*(__half2*)&kw1.y);
                float2 k2a = __half22float2(*(__half2*)&kw2.x), k2b = __half22float2(*(__half2*)&kw2.y);
                float2 k3a = __half22float2(*(__half2*)&kw3.x), k3b = __half22float2(*(__half2*)&kw3.y);
                #pragma unroll
                for (int p = 0; p < 4; p++) {
                    float4 q4 = *(const float4*)&Qs[(g * 32 + qi0 + p) * 64 + d];
                    sc[p][0] += q4.x * k0a.x + q4.y * k1a.x + q4.z * k2a.x + q4.w * k3a.x;
                    sc[p][1] += q4.x * k0a.y + q4.y * k1a.y + q4.z * k2a.y + q4.w * k3a.y;
                    sc[p][2] += q4.x * k0b.x + q4.y * k1b.x + q4.z * k2b.x + q4.w * k3b.x;
                    sc[p][3] += q4.x * k0b.y + q4.y * k1b.y + q4.z * k2b.y + q4.w * k3b.y;
                }
            }
            #pragma unroll
            for (int p = 0; p < 4; p++) {
                const int qg = q0 + qi0 + p;
                const int khi = qg - k0;
                int klo = qg - SWIN - k0; if (klo < 0) klo = 0;
                float v0 = (kk + 0 >= klo && kk + 0 <= khi) ? sc[p][0] * 0.125f : -INFINITY;
                float v1 = (kk + 1 >= klo && kk + 1 <= khi) ? sc[p][1] * 0.125f : -INFINITY;
                float v2 = (kk + 2 >= klo && kk + 2 <= khi) ? sc[p][2] * 0.125f : -INFINITY;
                float v3 = (kk + 3 >= klo && kk + 3 <= khi) ? sc[p][3] * 0.125f : -INFINITY;
                *(float4*)&S4[p * KT_STRIDE + kk] = make_float4(v0, v1, v2, v3);
                lmax[p] = fmaxf(lmax[p], fmaxf(fmaxf(v0, v1), fmaxf(v2, v3)));
            }
        }
        float inv[4];
        #pragma unroll
        for (int p = 0; p < 4; p++) {
            float m = lmax[p];
            #pragma unroll
            for (int o = 16; o; o >>= 1)
                m = fmaxf(m, __shfl_xor_sync(0xffffffffu, m, o));
            m = fmaxf(m, snk);
            float lsum = 0.f;
            for (int k = lane; k < KMAX; k += 32) {
                float e = expf(S4[p * KT_STRIDE + k] - m);
                S4[p * KT_STRIDE + k] = e;
                lsum += e;
            }
            #pragma unroll
            for (int o = 16; o; o >>= 1)
                lsum += __shfl_xor_sync(0xffffffffu, lsum, o);
            inv[p] = 1.f / (lsum + expf(snk - m));
        }
        __syncwarp();

        // ---- V pass: lane owns dim pair (2*lane, 2*lane+1) ----
        float a[4][2];
        #pragma unroll
        for (int p = 0; p < 4; p++) a[p][0] = a[p][1] = 0.f;
        for (int k = 0; k < kcnt; k++) {
            float2 v = __half22float2(*(__half2*)&Vs2[k * VS2 + lane]);
            #pragma unroll
            for (int p = 0; p < 4; p++) {
                float pp = S4[p * KT_STRIDE + k];
                a[p][0] += pp * v.x;
                a[p][1] += pp * v.y;
            }
        }
        #pragma unroll
        for (int p = 0; p < 4; p++) {
            const int qg = q0 + qi0 + p;
            *(__half2*)(g_ah + (size_t)qg * HDIM + h * HEADD + 2 * lane) =
                __floats2half2_rn(a[p][0] * inv[p], a[p][1] * inv[p]);
        }
        __syncwarp();
    }
}

// ---------------- launch ----------------
extern "C" void kernel_launch(void* const* d_in, const int* in_sizes, int n_in,
                              void* d_out, int out_size) {
    const float* x          = (const float*)d_in[0];
    const float* scale      = (const float*)d_in[1];
    const float* sinks      = (const float*)d_in[2];
    const float* qkv_kernel = (const float*)d_in[3];
    const float* qkv_bias   = (const float*)d_in[4];
    const float* out_kernel = (const float*)d_in[5];
    const float* out_bias   = (const float*)d_in[6];
    const float* cos_t      = (const float*)d_in[7];
    const float* sin_t      = (const float*)d_in[8];
    // d_in[9] = mask: unused (sliding window applied structurally)
    float* out = (float*)d_out;

    void *p_qkvh, *p_nh, *p_ah, *p_wqh, *p_woh;
    cudaGetSymbolAddress(&p_qkvh, g_qkvh);
    cudaGetSymbolAddress(&p_nh, g_nh);
    cudaGetSymbolAddress(&p_ah, g_ah);
    cudaGetSymbolAddress(&p_wqh, g_wqh);
    cudaGetSymbolAddress(&p_woh, g_woh);

    static bool attr_set = false;
    if (!attr_set) {
        cudaFuncSetAttribute(gemm_f16_1,
                             cudaFuncAttributeMaxDynamicSharedMemorySize, GSMEM_BYTES2);
        cudaFuncSetAttribute(attn5_kernel,
                             cudaFuncAttributeMaxDynamicSharedMemorySize, ATT5_BYTES);
        attr_set = true;
    }

    // transpose weights to fp16 [N][K]
    splitwh_t<<<dim3(QKVD / 32, HDIM / 32), dim3(32, 8)>>>(
        qkv_kernel, (__half*)p_wqh, HDIM, QKVD);
    splitwh_t<<<dim3(HDIM / 32, HDIM / 32), dim3(32, 8)>>>(
        out_kernel, (__half*)p_woh, HDIM, HDIM);

    rmsnorm_kernel<<<TT, 256>>>(x, scale);

    // QKV: fp16 1-term, writes fp16 qkv
    gemm_f16_1<<<dim3(QKVD / 128, TT / 128), 512, GSMEM_BYTES2>>>(
        (const __half*)p_nh, (const __half*)p_wqh,
        qkv_bias, nullptr, nullptr, (__half*)p_qkvh, QKVD, HDIM);

    // attention with fused rope
    attn5_kernel<<<dim3(TT / 32, NKVH), 512, ATT5_BYTES>>>(sinks, cos_t, sin_t);

    // out-proj + residual: fp16 1-term, fp32 out
    gemm_f16_1<<<dim3(HDIM / 128, TT / 128), 512, GSMEM_BYTES2>>>(
        (const __half*)p_ah, (const __half*)p_woh,
        out_bias, x, out, nullptr, HDIM, HDIM);
}

// round 15
// speedup vs baseline: 1.2783x; 1.2783x over previous
#include <cuda_runtime.h>
#include <cuda_bf16.h>
#include <cuda_fp16.h>
#include <stdint.h>
#include <math.h>

#define TT 2048
#define HDIM 2048
#define NHEADS 32
#define NKVH 8
#define HEADD 64
#define SWIN 128
#define QKVD 3072   // HEADD * (NHEADS + 2*NKVH)

// ---------------- scratch (device globals; no allocation allowed) ----------------
__device__ float g_qkv[(size_t)TT * QKVD];
__device__ __half g_nh[TT * HDIM];             // rmsnorm out, fp16
__device__ __half g_ah[TT * HDIM];             // attention out, fp16
__device__ __half g_wqh[(size_t)HDIM * QKVD];  // qkv weight fp16, transposed [N][K]
__device__ __half g_woh[(size_t)HDIM * HDIM];  // out weight fp16, transposed [N][K]

// ---------------- weight transpose to fp16: W[K][N] -> Wh[N][K] ---------
__global__ void splitwh_t(const float* __restrict__ W,
                          __half* __restrict__ Wh, int K, int N) {
    __shared__ float tile[32][33];
    const int kb = blockIdx.y * 32, nb = blockIdx.x * 32;
    const int tx = threadIdx.x, ty = threadIdx.y;   // 32 x 8
    #pragma unroll
    for (int i = 0; i < 32; i += 8)
        tile[ty + i][tx] = W[(size_t)(kb + ty + i) * N + nb + tx];
    __syncthreads();
    #pragma unroll
    for (int i = 0; i < 32; i += 8) {
        int n = nb + ty + i, k = kb + tx;
        Wh[(size_t)n * K + k] = __float2half(tile[tx][ty + i]);
    }
}

// ---------------- RMSNorm (writes fp16) ----------------
__global__ void rmsnorm_kernel(const float* __restrict__ x,
                               const float* __restrict__ scale) {
    int t = blockIdx.x;
    const float* row = x + (size_t)t * HDIM;
    float ss = 0.f;
    for (int i = threadIdx.x; i < HDIM; i += blockDim.x) {
        float v = row[i];
        ss += v * v;
    }
    __shared__ float sh[9];
    #pragma unroll
    for (int o = 16; o; o >>= 1) ss += __shfl_xor_sync(0xffffffffu, ss, o);
    int lane = threadIdx.x & 31, wid = threadIdx.x >> 5;
    if (lane == 0) sh[wid] = ss;
    __syncthreads();
    if (threadIdx.x == 0) {
        float s = 0.f;
        for (int i = 0; i < (int)(blockDim.x >> 5); i++) s += sh[i];
        sh[8] = rsqrtf(s / (float)HDIM + 1e-5f);
    }
    __syncthreads();
    float inv = sh[8];
    for (int i = threadIdx.x; i < HDIM; i += blockDim.x)
        g_nh[(size_t)t * HDIM + i] = __float2half(row[i] * inv * scale[i]);
}

// ---------------- GEMM pieces -------------------------------------------
#define MMAF(d, a, b0, b1) asm volatile( \
  "mma.sync.aligned.m16n8k16.row.col.f32.f16.f16.f32 " \
  "{%0,%1,%2,%3},{%4,%5,%6,%7},{%8,%9},{%0,%1,%2,%3};\n" \
  : "+f"((d)[0]), "+f"((d)[1]), "+f"((d)[2]), "+f"((d)[3]) \
  : "r"((a)[0]), "r"((a)[1]), "r"((a)[2]), "r"((a)[3]), \
    "r"(b0), "r"(b1))

#define LDSM4(r, addr) asm volatile( \
  "ldmatrix.sync.aligned.m8n8.x4.shared.b16 {%0,%1,%2,%3}, [%4];" \
  : "=r"((r)[0]), "=r"((r)[1]), "=r"((r)[2]), "=r"((r)[3]) : "r"(addr))

// BK = 64: row = 128 B data + 16 B pad -> conflict-free ldmatrix (4r mod 32 distinct)
#define SROWB 144u
#define SAB   (128u * SROWB)      // 18432 B per array
#define STAGEB2 (2u * SAB)        // A,B -> 36864 B per stage
#define GSMEM_BYTES2 (2 * STAGEB2)   // 73728 -> 2 CTAs/SM fit in 228KB

extern __shared__ unsigned char dynsm[];

// ---------------- fp16 1-term GEMM: A @ Bh + bias (+ resid), BK=64 -------------
__global__ __launch_bounds__(512, 2) void gemm_f16_1(
    const __half* __restrict__ A, const __half* __restrict__ Bh,
    const float* __restrict__ bias, const float* __restrict__ resid,
    float* __restrict__ C, int N, int K)
{
    const int tid  = threadIdx.x;
    const int lane = tid & 31;
    const int wid  = tid >> 5;
    const int grp  = lane >> 2;
    const int qid  = lane & 3;
    const int wm   = (wid >> 2) * 32;
    const int wn   = (wid & 3) * 32;
    const int m0 = blockIdx.y * 128;
    const int n0 = blockIdx.x * 128;

    uint32_t smb;
    asm("{ .reg .u64 t; cvta.to.shared.u64 t, %1; cvt.u32.u64 %0, t; }"
        : "=r"(smb) : "l"(dynsm));

    float acc[2][4][4];
    #pragma unroll
    for (int i = 0; i < 2; i++)
        #pragma unroll
        for (int j = 0; j < 4; j++)
            #pragma unroll
            for (int r = 0; r < 4; r++) acc[i][j][r] = 0.f;

    auto load_stage = [&](int stage, int t) {
        const int k0 = t << 6;
        const uint32_t sb = smb + stage * STAGEB2;
        #pragma unroll
        for (int i = 0; i < 2; i++) {
            int f = tid + 512 * i;
            int r = f >> 3;             // 0..127
            int cb = (f & 7) * 16;      // byte chunk in row
            {
                const __half* src = A + (size_t)(m0 + r) * K + k0 + (cb >> 1);
                uint32_t dst = sb + r * SROWB + cb;
                asm volatile("cp.async.cg.shared.global [%0], [%1], 16;" :: "r"(dst), "l"(src));
            }
            {
                const __half* src = Bh + (size_t)(n0 + r) * K + k0 + (cb >> 1);
                uint32_t dst = sb + SAB + r * SROWB + cb;
                asm volatile("cp.async.cg.shared.global [%0], [%1], 16;" :: "r"(dst), "l"(src));
            }
        }
        asm volatile("cp.async.commit_group;");
    };

    const uint32_t lmrow = lane & 15;
    const uint32_t lmkh  = (lane >> 4) * 16;
    const uint32_t aoff0 = (wm + 0  + lmrow) * SROWB + lmkh;
    const uint32_t aoff1 = (wm + 16 + lmrow) * SROWB + lmkh;
    const uint32_t boff0 = (wn + 0  + lmrow) * SROWB + lmkh;
    const uint32_t boff1 = (wn + 16 + lmrow) * SROWB + lmkh;

    const int trips = K >> 6;          // 32
    load_stage(0, 0);
    load_stage(1, 1);

    for (int t = 0; t < trips; t++) {
        if (t < trips - 1) asm volatile("cp.async.wait_group 1;");
        else               asm volatile("cp.async.wait_group 0;");
        __syncthreads();

        const uint32_t sb = smb + (t & 1) * STAGEB2;
        #pragma unroll
        for (int ks = 0; ks < 4; ks++) {
            const uint32_t ko = ks * 32;
            uint32_t ah[2][4];
            LDSM4(ah[0], sb + aoff0 + ko);
            LDSM4(ah[1], sb + aoff1 + ko);
            #pragma unroll
            for (int np = 0; np < 2; np++) {
                uint32_t bh[4];
                LDSM4(bh, sb + SAB + (np ? boff1 : boff0) + ko);
                #pragma unroll
                for (int mt = 0; mt < 2; mt++) {
                    #pragma unroll
                    for (int sub = 0; sub < 2; sub++) {
                        float* d = acc[mt][np * 2 + sub];
                        MMAF(d, ah[mt], bh[sub], bh[sub + 2]);
                    }
                }
            }
        }
        __syncthreads();
        if (t + 2 < trips) load_stage(t & 1, t + 2);
    }

    #pragma unroll
    for (int mt = 0; mt < 2; mt++) {
        int r0 = m0 + wm + mt * 16 + grp;
        #pragma unroll
        for (int nt = 0; nt < 4; nt++) {
            int c = n0 + wn + nt * 8 + qid * 2;
            float2 bb = *(const float2*)&bias[c];
            float2 v0 = make_float2(acc[mt][nt][0] + bb.x, acc[mt][nt][1] + bb.y);
            float2 v1 = make_float2(acc[mt][nt][2] + bb.x, acc[mt][nt][3] + bb.y);
            if (resid) {
                float2 ra = *(const float2*)&resid[(size_t)r0 * N + c];
                float2 rb = *(const float2*)&resid[(size_t)(r0 + 8) * N + c];
                v0.x += ra.x; v0.y += ra.y; v1.x += rb.x; v1.y += rb.y;
            }
            *(float2*)&C[(size_t)r0 * N + c]       = v0;
            *(float2*)&C[(size_t)(r0 + 8) * N + c] = v1;
        }
    }
}

// ---------------- RoPE (in-place on g_qkv) ----------------
__global__ void rope_kernel(const float* __restrict__ cos_t,
                            const float* __restrict__ sin_t) {
    int t = blockIdx.x;
    const float* c = cos_t + t * 32;
    const float* s = sin_t + t * 32;
    float* rowbase = g_qkv + (size_t)t * QKVD;
    for (int i = threadIdx.x; i < 40 * 32; i += blockDim.x) {
        int head = i >> 5, r = i & 31;
        float* base = rowbase + head * HEADD;
        float x1 = base[r], x2 = base[r + 32];
        float cv = c[r], sv = s[r];
        base[r]      = x1 * cv - x2 * sv;
        base[r + 32] = x2 * cv + x1 * sv;
    }
}

// ---------------- tiled sliding-window GQA attention with sink ----------------
#define KMAX 160
#define KT_STRIDE 164
#define V_STRIDE 68
#define OFF_KT 0
#define OFF_V  (64 * KT_STRIDE)                    // 10496
#define OFF_Q  (OFF_V + KMAX * V_STRIDE)           // 21376
#define OFF_S  (OFF_Q + 4 * 32 * 64)               // 29568
#define ATT_SMEM_FLOATS (OFF_S + 16 * 4 * KT_STRIDE)  // 40064 -> 160256 B

__global__ __launch_bounds__(512, 1) void attn4_kernel(const float* __restrict__ sinks) {
    float* smf = (float*)dynsm;
    float* KsT = smf + OFF_KT;
    float* Vs  = smf + OFF_V;
    float* Qs  = smf + OFF_Q;
    float* S   = smf + OFF_S;

    const int qt = blockIdx.x;
    const int n  = blockIdx.y;
    const int q0 = qt * 32;
    const int k0 = (q0 - SWIN > 0) ? (q0 - SWIN) : 0;
    const int kcnt = q0 + 32 - k0;
    const int tid = threadIdx.x;
    const int lane = tid & 31, wid = tid >> 5;

    const float* kbase = g_qkv + (size_t)k0 * QKVD + NHEADS * HEADD + n * HEADD;
    const float* vbase = kbase + NKVH * HEADD;

    for (int f = tid; f < kcnt * 16; f += 512) {
        int r = f >> 4, dq = (f & 15) * 4;
        float4 kv = *(const float4*)(kbase + (size_t)r * QKVD + dq);
        KsT[(dq + 0) * KT_STRIDE + r] = kv.x;
        KsT[(dq + 1) * KT_STRIDE + r] = kv.y;
        KsT[(dq + 2) * KT_STRIDE + r] = kv.z;
        KsT[(dq + 3) * KT_STRIDE + r] = kv.w;
        float4 vv = *(const float4*)(vbase + (size_t)r * QKVD + dq);
        *(float4*)&Vs[r * V_STRIDE + dq] = vv;
    }
    for (int f = tid; f < 4 * 32 * 16; f += 512) {
        int g = f >> 9, r = (f >> 4) & 31, dq = (f & 15) * 4;
        *(float4*)&Qs[(g * 32 + r) * 64 + dq] =
            *(const float4*)(g_qkv + (size_t)(q0 + r) * QKVD + (n * 4 + g) * HEADD + dq);
    }
    __syncthreads();

    const int g  = wid & 3;
    const int ww = wid >> 2;
    const int h  = n * 4 + g;
    const float snk = sinks[h];
    float* S4 = S + wid * 4 * KT_STRIDE;

    #pragma unroll
    for (int qq = 0; qq < 2; qq++) {
        const int qi0 = ww * 8 + qq * 4;
        float lmax[4] = {-INFINITY, -INFINITY, -INFINITY, -INFINITY};

        for (int kb = lane; kb < 40; kb += 32) {
            const int kk = kb * 4;
            float sc[4][4];
            #pragma unroll
            for (int p = 0; p < 4; p++)
                sc[p][0] = sc[p][1] = sc[p][2] = sc[p][3] = 0.f;
            #pragma unroll
            for (int d = 0; d < 64; d += 4) {
                float4 kv0 = *(const float4*)&KsT[(d + 0) * KT_STRIDE + kk];
                float4 kv1 = *(const float4*)&KsT[(d + 1) * KT_STRIDE + kk];
                float4 kv2 = *(const float4*)&KsT[(d + 2) * KT_STRIDE + kk];
                float4 kv3 = *(const float4*)&KsT[(d + 3) * KT_STRIDE + kk];
                #pragma unroll
                for (int p = 0; p < 4; p++) {
                    float4 q4 = *(const float4*)&Qs[(g * 32 + qi0 + p) * 64 + d];
                    sc[p][0] += q4.x * kv0.x + q4.y * kv1.x + q4.z * kv2.x + q4.w * kv3.x;
                    sc[p][1] += q4.x * kv0.y + q4.y * kv1.y + q4.z * kv2.y + q4.w * kv3.y;
                    sc[p][2] += q4.x * kv0.z + q4.y * kv1.z + q4.z * kv2.z + q4.w * kv3.z;
                    sc[p][3] += q4.x * kv0.w + q4.y * kv1.w + q4.z * kv2.w + q4.w * kv3.w;
                }
            }
            #pragma unroll
            for (int p = 0; p < 4; p++) {
                const int qg = q0 + qi0 + p;
                const int khi = qg - k0;
                int klo = qg - SWIN - k0; if (klo < 0) klo = 0;
                float v0 = (kk + 0 >= klo && kk + 0 <= khi) ? sc[p][0] * 0.125f : -INFINITY;
                float v1 = (kk + 1 >= klo && kk + 1 <= khi) ? sc[p][1] * 0.125f : -INFINITY;
                float v2 = (kk + 2 >= klo && kk + 2 <= khi) ? sc[p][2] * 0.125f : -INFINITY;
                float v3 = (kk + 3 >= klo && kk + 3 <= khi) ? sc[p][3] * 0.125f : -INFINITY;
                *(float4*)&S4[p * KT_STRIDE + kk] = make_float4(v0, v1, v2, v3);
                lmax[p] = fmaxf(lmax[p], fmaxf(fmaxf(v0, v1), fmaxf(v2, v3)));
            }
        }
        float inv[4];
        #pragma unroll
        for (int p = 0; p < 4; p++) {
            float m = lmax[p];
            #pragma unroll
            for (int o = 16; o; o >>= 1)
                m = fmaxf(m, __shfl_xor_sync(0xffffffffu, m, o));
            m = fmaxf(m, snk);
            float lsum = 0.f;
            for (int k = lane; k < KMAX; k += 32) {
                float e = expf(S4[p * KT_STRIDE + k] - m);
                S4[p * KT_STRIDE + k] = e;
                lsum += e;
            }
            #pragma unroll
            for (int o = 16; o; o >>= 1)
                lsum += __shfl_xor_sync(0xffffffffu, lsum, o);
            inv[p] = 1.f / (lsum + expf(snk - m));
        }
        __syncwarp();

        float a[4][2];
        #pragma unroll
        for (int p = 0; p < 4; p++) a[p][0] = a[p][1] = 0.f;
        const int d0 = lane, d1 = lane + 32;
        for (int k = 0; k < kcnt; k++) {
            float v0 = Vs[k * V_STRIDE + d0];
            float v1 = Vs[k * V_STRIDE + d1];
            #pragma unroll
            for (int p = 0; p < 4; p++) {
                float pp = S4[p * KT_STRIDE + k];
                a[p][0] += pp * v0;
                a[p][1] += pp * v1;
            }
        }
        #pragma unroll
        for (int p = 0; p < 4; p++) {
            const int qg = q0 + qi0 + p;
            size_t o0 = (size_t)qg * HDIM + h * HEADD;
            g_ah[o0 + d0] = __float2half(a[p][0] * inv[p]);
            g_ah[o0 + d1] = __float2half(a[p][1] * inv[p]);
        }
        __syncwarp();
    }
}

// ---------------- launch ----------------
extern "C" void kernel_launch(void* const* d_in, const int* in_sizes, int n_in,
                              void* d_out, int out_size) {
    const float* x          = (const float*)d_in[0];
    const float* scale      = (const float*)d_in[1];
    const float* sinks      = (const float*)d_in[2];
    const float* qkv_kernel = (const float*)d_in[3];
    const float* qkv_bias   = (const float*)d_in[4];
    const float* out_kernel = (const float*)d_in[5];
    const float* out_bias   = (const float*)d_in[6];
    const float* cos_t      = (const float*)d_in[7];
    const float* sin_t      = (const float*)d_in[8];
    // d_in[9] = mask: unused (sliding window applied structurally)
    float* out = (float*)d_out;

    void *p_qkv, *p_nh, *p_ah, *p_wqh, *p_woh;
    cudaGetSymbolAddress(&p_qkv, g_qkv);
    cudaGetSymbolAddress(&p_nh, g_nh);
    cudaGetSymbolAddress(&p_ah, g_ah);
    cudaGetSymbolAddress(&p_wqh, g_wqh);
    cudaGetSymbolAddress(&p_woh, g_woh);

    static bool attr_set = false;
    if (!attr_set) {
        cudaFuncSetAttribute(gemm_f16_1,
                             cudaFuncAttributeMaxDynamicSharedMemorySize, GSMEM_BYTES2);
        cudaFuncSetAttribute(attn4_kernel,
                             cudaFuncAttributeMaxDynamicSharedMemorySize,
                             ATT_SMEM_FLOATS * 4);
        attr_set = true;
    }

    // transpose weights to fp16 [N][K]
    splitwh_t<<<dim3(QKVD / 32, HDIM / 32), dim3(32, 8)>>>(
        qkv_kernel, (__half*)p_wqh, HDIM, QKVD);
    splitwh_t<<<dim3(HDIM / 32, HDIM / 32), dim3(32, 8)>>>(
        out_kernel, (__half*)p_woh, HDIM, HDIM);

    rmsnorm_kernel<<<TT, 256>>>(x, scale);

    // QKV: fp16 1-term [2048,2048] @ [2048,3072]
    gemm_f16_1<<<dim3(QKVD / 128, TT / 128), 512, GSMEM_BYTES2>>>(
        (const __half*)p_nh, (const __half*)p_wqh,
        qkv_bias, nullptr, (float*)p_qkv, QKVD, HDIM);

    rope_kernel<<<TT, 256>>>(cos_t, sin_t);

    attn4_kernel<<<dim3(TT / 32, NKVH), 512, ATT_SMEM_FLOATS * 4>>>(sinks);

    // out-proj + residual: fp16 1-term
    gemm_f16_1<<<dim3(HDIM / 128, TT / 128), 512, GSMEM_BYTES2>>>(
        (const __half*)p_ah, (const __half*)p_woh,
        out_bias, x, out, HDIM, HDIM);
}

// round 16
// speedup vs baseline: 1.2964x; 1.0142x over previous
#include <cuda_runtime.h>
#include <cuda_bf16.h>
#include <cuda_fp16.h>
#include <stdint.h>
#include <math.h>

#define TT 2048
#define HDIM 2048
#define NHEADS 32
#define NKVH 8
#define HEADD 64
#define SWIN 128
#define QKVD 3072   // HEADD * (NHEADS + 2*NKVH)
#define ROPE_END 2560   // q (2048) + k (512) columns get rope; v beyond

// ---------------- scratch (device globals; no allocation allowed) ----------------
__device__ __half g_qkvh[(size_t)TT * QKVD];   // qkv, fp16, rope already applied
__device__ __half g_nh[TT * HDIM];             // rmsnorm out, fp16
__device__ __half g_ah[TT * HDIM];             // attention out, fp16
__device__ __half g_wqh[(size_t)HDIM * QKVD];  // qkv weight fp16, transposed [N][K]
__device__ __half g_woh[(size_t)HDIM * HDIM];  // out weight fp16, transposed [N][K]

// ---------------- weight transpose to fp16: W[K][N] -> Wh[N][K] ---------
__global__ void splitwh_t(const float* __restrict__ W,
                          __half* __restrict__ Wh, int K, int N) {
    __shared__ float tile[32][33];
    const int kb = blockIdx.y * 32, nb = blockIdx.x * 32;
    const int tx = threadIdx.x, ty = threadIdx.y;   // 32 x 8
    #pragma unroll
    for (int i = 0; i < 32; i += 8)
        tile[ty + i][tx] = W[(size_t)(kb + ty + i) * N + nb + tx];
    __syncthreads();
    #pragma unroll
    for (int i = 0; i < 32; i += 8) {
        int n = nb + ty + i, k = kb + tx;
        Wh[(size_t)n * K + k] = __float2half(tile[tx][ty + i]);
    }
}

// ---------------- RMSNorm (writes fp16) ----------------
__global__ void rmsnorm_kernel(const float* __restrict__ x,
                               const float* __restrict__ scale) {
    int t = blockIdx.x;
    const float* row = x + (size_t)t * HDIM;
    float ss = 0.f;
    for (int i = threadIdx.x; i < HDIM; i += blockDim.x) {
        float v = row[i];
        ss += v * v;
    }
    __shared__ float sh[9];
    #pragma unroll
    for (int o = 16; o; o >>= 1) ss += __shfl_xor_sync(0xffffffffu, ss, o);
    int lane = threadIdx.x & 31, wid = threadIdx.x >> 5;
    if (lane == 0) sh[wid] = ss;
    __syncthreads();
    if (threadIdx.x == 0) {
        float s = 0.f;
        for (int i = 0; i < (int)(blockDim.x >> 5); i++) s += sh[i];
        sh[8] = rsqrtf(s / (float)HDIM + 1e-5f);
    }
    __syncthreads();
    float inv = sh[8];
    for (int i = threadIdx.x; i < HDIM; i += blockDim.x)
        g_nh[(size_t)t * HDIM + i] = __float2half(row[i] * inv * scale[i]);
}

// ---------------- GEMM pieces -------------------------------------------
#define MMAF(d, a, b0, b1) asm volatile( \
  "mma.sync.aligned.m16n8k16.row.col.f32.f16.f16.f32 " \
  "{%0,%1,%2,%3},{%4,%5,%6,%7},{%8,%9},{%0,%1,%2,%3};\n" \
  : "+f"((d)[0]), "+f"((d)[1]), "+f"((d)[2]), "+f"((d)[3]) \
  : "r"((a)[0]), "r"((a)[1]), "r"((a)[2]), "r"((a)[3]), \
    "r"(b0), "r"(b1))

#define LDSM4(r, addr) asm volatile( \
  "ldmatrix.sync.aligned.m8n8.x4.shared.b16 {%0,%1,%2,%3}, [%4];" \
  : "=r"((r)[0]), "=r"((r)[1]), "=r"((r)[2]), "=r"((r)[3]) : "r"(addr))

// BK = 64: row = 128 B data + 16 B pad -> conflict-free ldmatrix
#define SROWB 144u
#define SAB   (128u * SROWB)      // 18432 B per array
#define STAGEB2 (2u * SAB)        // A,B -> 36864 B per stage
#define GSMEM_BYTES2 (2 * STAGEB2)   // 73728 -> 2 CTAs/SM

extern __shared__ unsigned char dynsm[];

// ============ shared GEMM mainloop (BK=64) as a macro-like inline ============
#define GEMM_MAINLOOP(A_, B_, K_) \
    float acc[2][4][4]; \
    _Pragma("unroll") \
    for (int i = 0; i < 2; i++) \
        _Pragma("unroll") \
        for (int j = 0; j < 4; j++) \
            _Pragma("unroll") \
            for (int r = 0; r < 4; r++) acc[i][j][r] = 0.f; \
    auto load_stage = [&](int stage, int t) { \
        const int k0 = t << 6; \
        const uint32_t sb = smb + stage * STAGEB2; \
        _Pragma("unroll") \
        for (int i = 0; i < 2; i++) { \
            int f = tid + 512 * i; \
            int r = f >> 3; \
            int cb = (f & 7) * 16; \
            { \
                const __half* src = A_ + (size_t)(m0 + r) * K_ + k0 + (cb >> 1); \
                uint32_t dst = sb + r * SROWB + cb; \
                asm volatile("cp.async.cg.shared.global [%0], [%1], 16;" :: "r"(dst), "l"(src)); \
            } \
            { \
                const __half* src = B_ + (size_t)(n0 + r) * K_ + k0 + (cb >> 1); \
                uint32_t dst = sb + SAB + r * SROWB + cb; \
                asm volatile("cp.async.cg.shared.global [%0], [%1], 16;" :: "r"(dst), "l"(src)); \
            } \
        } \
        asm volatile("cp.async.commit_group;"); \
    }; \
    const uint32_t lmrow = lane & 15; \
    const uint32_t lmkh  = (lane >> 4) * 16; \
    const uint32_t aoff0 = (wm + 0  + lmrow) * SROWB + lmkh; \
    const uint32_t aoff1 = (wm + 16 + lmrow) * SROWB + lmkh; \
    const uint32_t boff0 = (wn + 0  + lmrow) * SROWB + lmkh; \
    const uint32_t boff1 = (wn + 16 + lmrow) * SROWB + lmkh; \
    const int trips = K_ >> 6; \
    load_stage(0, 0); \
    load_stage(1, 1); \
    for (int t = 0; t < trips; t++) { \
        if (t < trips - 1) asm volatile("cp.async.wait_group 1;"); \
        else               asm volatile("cp.async.wait_group 0;"); \
        __syncthreads(); \
        const uint32_t sb = smb + (t & 1) * STAGEB2; \
        _Pragma("unroll") \
        for (int ks = 0; ks < 4; ks++) { \
            const uint32_t ko = ks * 32; \
            uint32_t ah[2][4]; \
            LDSM4(ah[0], sb + aoff0 + ko); \
            LDSM4(ah[1], sb + aoff1 + ko); \
            _Pragma("unroll") \
            for (int np = 0; np < 2; np++) { \
                uint32_t bh[4]; \
                LDSM4(bh, sb + SAB + (np ? boff1 : boff0) + ko); \
                _Pragma("unroll") \
                for (int mt = 0; mt < 2; mt++) { \
                    _Pragma("unroll") \
                    for (int sub = 0; sub < 2; sub++) { \
                        float* d = acc[mt][np * 2 + sub]; \
                        MMAF(d, ah[mt], bh[sub], bh[sub + 2]); \
                    } \
                } \
            } \
        } \
        __syncthreads(); \
        if (t + 2 < trips) load_stage(t & 1, t + 2); \
    }

// ---------------- QKV GEMM with rope epilogue, fp16 output ---------------------
__global__ __launch_bounds__(512, 2) void gemm_qkv_rope(
    const __half* __restrict__ A, const __half* __restrict__ Bh,
    const float* __restrict__ bias,
    const float* __restrict__ cos_t, const float* __restrict__ sin_t,
    int N, int K)
{
    const int tid  = threadIdx.x;
    const int lane = tid & 31;
    const int wid  = tid >> 5;
    const int grp  = lane >> 2;
    const int qid  = lane & 3;
    const int wm   = (wid >> 2) * 32;
    const int wn   = (wid & 3) * 32;
    const int m0 = blockIdx.y * 128;
    const int n0 = blockIdx.x * 128;

    uint32_t smb;
    asm("{ .reg .u64 t; cvta.to.shared.u64 t, %1; cvt.u32.u64 %0, t; }"
        : "=r"(smb) : "l"(dynsm));

    GEMM_MAINLOOP(A, Bh, K)

    // epilogue: acc + bias -> smem stage -> rope pairs -> fp16 global
    __syncthreads();
    float* stage = (float*)dynsm;     // [128][132]
    #pragma unroll
    for (int mt = 0; mt < 2; mt++) {
        int rl = wm + mt * 16 + grp;
        #pragma unroll
        for (int nt = 0; nt < 4; nt++) {
            int c = wn + nt * 8 + qid * 2;
            float2 bb = *(const float2*)&bias[n0 + c];
            stage[rl * 132 + c]           = acc[mt][nt][0] + bb.x;
            stage[rl * 132 + c + 1]       = acc[mt][nt][1] + bb.y;
            stage[(rl + 8) * 132 + c]     = acc[mt][nt][2] + bb.x;
            stage[(rl + 8) * 132 + c + 1] = acc[mt][nt][3] + bb.y;
        }
    }
    __syncthreads();
    const bool do_rope = (n0 < ROPE_END);
    for (int f = tid; f < 128 * 32; f += 512) {
        int r = f >> 5;                 // local row
        int u = f & 31;                 // hh*16 + rr/2
        int hh = u >> 4, rr = (u & 15) * 2;
        int c1 = hh * 64 + rr;
        float a0 = stage[r * 132 + c1],      a1 = stage[r * 132 + c1 + 1];
        float b0 = stage[r * 132 + c1 + 32], b1 = stage[r * 132 + c1 + 33];
        int m = m0 + r;
        float o0, o1, o2, o3;
        if (do_rope) {
            float2 cs = *(const float2*)&cos_t[(size_t)m * 32 + rr];
            float2 sn = *(const float2*)&sin_t[(size_t)m * 32 + rr];
            o0 = a0 * cs.x - b0 * sn.x;
            o1 = a1 * cs.y - b1 * sn.y;
            o2 = b0 * cs.x + a0 * sn.x;
            o3 = b1 * cs.y + a1 * sn.y;
        } else {
            o0 = a0; o1 = a1; o2 = b0; o3 = b1;
        }
        __half* dst = g_qkvh + (size_t)m * QKVD + n0;
        *(__half2*)(dst + c1)      = __floats2half2_rn(o0, o1);
        *(__half2*)(dst + c1 + 32) = __floats2half2_rn(o2, o3);
    }
}

// ---------------- fp16 1-term GEMM (out-proj): A @ Bh + bias + resid -> fp32 ----
__global__ __launch_bounds__(512, 2) void gemm_f16_1(
    const __half* __restrict__ A, const __half* __restrict__ Bh,
    const float* __restrict__ bias, const float* __restrict__ resid,
    float* __restrict__ C, int N, int K)
{
    const int tid  = threadIdx.x;
    const int lane = tid & 31;
    const int wid  = tid >> 5;
    const int grp  = lane >> 2;
    const int qid  = lane & 3;
    const int wm   = (wid >> 2) * 32;
    const int wn   = (wid & 3) * 32;
    const int m0 = blockIdx.y * 128;
    const int n0 = blockIdx.x * 128;

    uint32_t smb;
    asm("{ .reg .u64 t; cvta.to.shared.u64 t, %1; cvt.u32.u64 %0, t; }"
        : "=r"(smb) : "l"(dynsm));

    GEMM_MAINLOOP(A, Bh, K)

    #pragma unroll
    for (int mt = 0; mt < 2; mt++) {
        int r0 = m0 + wm + mt * 16 + grp;
        #pragma unroll
        for (int nt = 0; nt < 4; nt++) {
            int c = n0 + wn + nt * 8 + qid * 2;
            float2 bb = *(const float2*)&bias[c];
            float2 ra = *(const float2*)&resid[(size_t)r0 * N + c];
            float2 rb = *(const float2*)&resid[(size_t)(r0 + 8) * N + c];
            float2 v0 = make_float2(acc[mt][nt][0] + bb.x + ra.x,
                                    acc[mt][nt][1] + bb.y + ra.y);
            float2 v1 = make_float2(acc[mt][nt][2] + bb.x + rb.x,
                                    acc[mt][nt][3] + bb.y + rb.y);
            *(float2*)&C[(size_t)r0 * N + c]       = v0;
            *(float2*)&C[(size_t)(r0 + 8) * N + c] = v1;
        }
    }
}

// ---------------- tiled sliding-window GQA attention with sink ----------------
// reads fp16 qkv (rope pre-applied); converts to fp32 ONCE at staging;
// inner loops identical to the proven attn4.
#define KMAX 160
#define KT_STRIDE 164
#define V_STRIDE 68
#define OFF_KT 0
#define OFF_V  (64 * KT_STRIDE)                    // 10496
#define OFF_Q  (OFF_V + KMAX * V_STRIDE)           // 21376
#define OFF_S  (OFF_Q + 4 * 32 * 64)               // 29568
#define ATT_SMEM_FLOATS (OFF_S + 16 * 4 * KT_STRIDE)  // 40064 -> 160256 B

__global__ __launch_bounds__(512, 1) void attn4h_kernel(const float* __restrict__ sinks) {
    float* smf = (float*)dynsm;
    float* KsT = smf + OFF_KT;
    float* Vs  = smf + OFF_V;
    float* Qs  = smf + OFF_Q;
    float* S   = smf + OFF_S;

    const int qt = blockIdx.x;
    const int n  = blockIdx.y;
    const int q0 = qt * 32;
    const int k0 = (q0 - SWIN > 0) ? (q0 - SWIN) : 0;
    const int kcnt = q0 + 32 - k0;
    const int tid = threadIdx.x;
    const int lane = tid & 31, wid = tid >> 5;

    const __half* kbase = g_qkvh + (size_t)k0 * QKVD + NHEADS * HEADD + n * HEADD;
    const __half* vbase = kbase + NKVH * HEADD;

    for (int f = tid; f < kcnt * 16; f += 512) {
        int r = f >> 4, dq = (f & 15) * 4;
        uint2 kw = *(const uint2*)(kbase + (size_t)r * QKVD + dq);
        float2 ka = __half22float2(*(__half2*)&kw.x);
        float2 kb = __half22float2(*(__half2*)&kw.y);
        KsT[(dq + 0) * KT_STRIDE + r] = ka.x;
        KsT[(dq + 1) * KT_STRIDE + r] = ka.y;
        KsT[(dq + 2) * KT_STRIDE + r] = kb.x;
        KsT[(dq + 3) * KT_STRIDE + r] = kb.y;
        uint2 vw = *(const uint2*)(vbase + (size_t)r * QKVD + dq);
        float2 va = __half22float2(*(__half2*)&vw.x);
        float2 vb = __half22float2(*(__half2*)&vw.y);
        *(float4*)&Vs[r * V_STRIDE + dq] = make_float4(va.x, va.y, vb.x, vb.y);
    }
    for (int f = tid; f < 4 * 32 * 16; f += 512) {
        int g = f >> 9, r = (f >> 4) & 31, dq = (f & 15) * 4;
        uint2 qw = *(const uint2*)(g_qkvh + (size_t)(q0 + r) * QKVD + (n * 4 + g) * HEADD + dq);
        float2 qa = __half22float2(*(__half2*)&qw.x);
        float2 qb = __half22float2(*(__half2*)&qw.y);
        *(float4*)&Qs[(g * 32 + r) * 64 + dq] = make_float4(qa.x, qa.y, qb.x, qb.y);
    }
    __syncthreads();

    const int g  = wid & 3;
    const int ww = wid >> 2;
    const int h  = n * 4 + g;
    const float snk = sinks[h];
    float* S4 = S + wid * 4 * KT_STRIDE;

    #pragma unroll
    for (int qq = 0; qq < 2; qq++) {
        const int qi0 = ww * 8 + qq * 4;
        float lmax[4] = {-INFINITY, -INFINITY, -INFINITY, -INFINITY};

        for (int kb = lane; kb < 40; kb += 32) {
            const int kk = kb * 4;
            float sc[4][4];
            #pragma unroll
            for (int p = 0; p < 4; p++)
                sc[p][0] = sc[p][1] = sc[p][2] = sc[p][3] = 0.f;
            #pragma unroll
            for (int d = 0; d < 64; d += 4) {
                float4 kv0 = *(const float4*)&KsT[(d + 0) * KT_STRIDE + kk];
                float4 kv1 = *(const float4*)&KsT[(d + 1) * KT_STRIDE + kk];
                float4 kv2 = *(const float4*)&KsT[(d + 2) * KT_STRIDE + kk];
                float4 kv3 = *(const float4*)&KsT[(d + 3) * KT_STRIDE + kk];
                #pragma unroll
                for (int p = 0; p < 4; p++) {
                    float4 q4 = *(const float4*)&Qs[(g * 32 + qi0 + p) * 64 + d];
                    sc[p][0] += q4.x * kv0.x + q4.y * kv1.x + q4.z * kv2.x + q4.w * kv3.x;
                    sc[p][1] += q4.x * kv0.y + q4.y * kv1.y + q4.z * kv2.y + q4.w * kv3.y;
                    sc[p][2] += q4.x * kv0.z + q4.y * kv1.z + q4.z * kv2.z + q4.w * kv3.z;
                    sc[p][3] += q4.x * kv0.w + q4.y * kv1.w + q4.z * kv2.w + q4.w * kv3.w;
                }
            }
            #pragma unroll
            for (int p = 0; p < 4; p++) {
                const int qg = q0 + qi0 + p;
                const int khi = qg - k0;
                int klo = qg - SWIN - k0; if (klo < 0) klo = 0;
                float v0 = (kk + 0 >= klo && kk + 0 <= khi) ? sc[p][0] * 0.125f : -INFINITY;
                float v1 = (kk + 1 >= klo && kk + 1 <= khi) ? sc[p][1] * 0.125f : -INFINITY;
                float v2 = (kk + 2 >= klo && kk + 2 <= khi) ? sc[p][2] * 0.125f : -INFINITY;
                float v3 = (kk + 3 >= klo && kk + 3 <= khi) ? sc[p][3] * 0.125f : -INFINITY;
                *(float4*)&S4[p * KT_STRIDE + kk] = make_float4(v0, v1, v2, v3);
                lmax[p] = fmaxf(lmax[p], fmaxf(fmaxf(v0, v1), fmaxf(v2, v3)));
            }
        }
        float inv[4];
        #pragma unroll
        for (int p = 0; p < 4; p++) {
            float m = lmax[p];
            #pragma unroll
            for (int o = 16; o; o >>= 1)
                m = fmaxf(m, __shfl_xor_sync(0xffffffffu, m, o));
            m = fmaxf(m, snk);
            float lsum = 0.f;
            for (int k = lane; k < KMAX; k += 32) {
                float e = expf(S4[p * KT_STRIDE + k] - m);
                S4[p * KT_STRIDE + k] = e;
                lsum += e;
            }
            #pragma unroll
            for (int o = 16; o; o >>= 1)
                lsum += __shfl_xor_sync(0xffffffffu, lsum, o);
            inv[p] = 1.f / (lsum + expf(snk - m));
        }
        __syncwarp();

        float a[4][2];
        #pragma unroll
        for (int p = 0; p < 4; p++) a[p][0] = a[p][1] = 0.f;
        const int d0 = lane, d1 = lane + 32;
        for (int k = 0; k < kcnt; k++) {
            float v0 = Vs[k * V_STRIDE + d0];
            float v1 = Vs[k * V_STRIDE + d1];
            #pragma unroll
            for (int p = 0; p < 4; p++) {
                float pp = S4[p * KT_STRIDE + k];
                a[p][0] += pp * v0;
                a[p][1] += pp * v1;
            }
        }
        #pragma unroll
        for (int p = 0; p < 4; p++) {
            const int qg = q0 + qi0 + p;
            size_t o0 = (size_t)qg * HDIM + h * HEADD;
            g_ah[o0 + d0] = __float2half(a[p][0] * inv[p]);
            g_ah[o0 + d1] = __float2half(a[p][1] * inv[p]);
        }
        __syncwarp();
    }
}

// ---------------- launch ----------------
extern "C" void kernel_launch(void* const* d_in, const int* in_sizes, int n_in,
                              void* d_out, int out_size) {
    const float* x          = (const float*)d_in[0];
    const float* scale      = (const float*)d_in[1];
    const float* sinks      = (const float*)d_in[2];
    const float* qkv_kernel = (const float*)d_in[3];
    const float* qkv_bias   = (const float*)d_in[4];
    const float* out_kernel = (const float*)d_in[5];
    const float* out_bias   = (const float*)d_in[6];
    const float* cos_t      = (const float*)d_in[7];
    const float* sin_t      = (const float*)d_in[8];
    // d_in[9] = mask: unused (sliding window applied structurally)
    float* out = (float*)d_out;

    void *p_nh, *p_ah, *p_wqh, *p_woh;
    cudaGetSymbolAddress(&p_nh, g_nh);
    cudaGetSymbolAddress(&p_ah, g_ah);
    cudaGetSymbolAddress(&p_wqh, g_wqh);
    cudaGetSymbolAddress(&p_woh, g_woh);

    static bool attr_set = false;
    if (!attr_set) {
        cudaFuncSetAttribute(gemm_qkv_rope,
                             cudaFuncAttributeMaxDynamicSharedMemorySize, GSMEM_BYTES2);
        cudaFuncSetAttribute(gemm_f16_1,
                             cudaFuncAttributeMaxDynamicSharedMemorySize, GSMEM_BYTES2);
        cudaFuncSetAttribute(attn4h_kernel,
                             cudaFuncAttributeMaxDynamicSharedMemorySize,
                             ATT_SMEM_FLOATS * 4);
        attr_set = true;
    }

    // transpose weights to fp16 [N][K]
    splitwh_t<<<dim3(QKVD / 32, HDIM / 32), dim3(32, 8)>>>(
        qkv_kernel, (__half*)p_wqh, HDIM, QKVD);
    splitwh_t<<<dim3(HDIM / 32, HDIM / 32), dim3(32, 8)>>>(
        out_kernel, (__half*)p_woh, HDIM, HDIM);

    rmsnorm_kernel<<<TT, 256>>>(x, scale);

    // QKV GEMM + fused rope, fp16 output
    gemm_qkv_rope<<<dim3(QKVD / 128, TT / 128), 512, GSMEM_BYTES2>>>(
        (const __half*)p_nh, (const __half*)p_wqh,
        qkv_bias, cos_t, sin_t, QKVD, HDIM);

    attn4h_kernel<<<dim3(TT / 32, NKVH), 512, ATT_SMEM_FLOATS * 4>>>(sinks);

    // out-proj + residual: fp16 1-term, fp32 out
    gemm_f16_1<<<dim3(HDIM / 128, TT / 128), 512, GSMEM_BYTES2>>>(
        (const __half*)p_ah, (const __half*)p_woh,
        out_bias, x, out, HDIM, HDIM);
}